// round 1
// baseline (speedup 1.0000x reference)
#include <cuda_runtime.h>
#include <cstdint>

#define NTOK 8192
#define HCH  2048
#define DHEAD 128

// -------- scratch (device globals; no allocation allowed) --------
__device__ float g_qkv[NTOK * 384];     // [N][384] : q|k|v
__device__ float g_qt[DHEAD * NTOK];    // Q^T [128][8192], pre-scaled by log2(e)/128
__device__ float g_kt[DHEAD * NTOK];    // K^T [128][8192]
__device__ int   g_mask4;               // 1 if mask elements are 4-byte, 0 if 1-byte

__device__ __forceinline__ float fexp2(float x) {
  float y;
  asm("ex2.approx.ftz.f32 %0, %1;" : "=f"(y) : "f"(x));
  return y;
}

// ---------------- mask dtype detection ----------------
// 4-byte elements (int32 0/1 or float32 0.0/1.0) -> every word in {0,1,0x3f800000}.
// 1-byte bools pack 4 random 0/1 bytes per word -> P(word looks 4-byte) ~ 1/8,
// over 64 words the misclassification probability is ~8^-64.
__global__ void detect_mask_kernel(const unsigned* __restrict__ m) {
  if (threadIdx.x == 0 && blockIdx.x == 0) {
    int ok = 1;
    for (int i = 0; i < 64; i++) {
      unsigned w = m[i];
      if (w > 1u && w != 0x3f800000u) { ok = 0; break; }
    }
    g_mask4 = ok;
  }
}

// ---------------- QKV GEMM ----------------
// g_qkv[m][n] = sum_k x[m][k] * w[n][k];  M=8192, N=384, K=2048 (both K-major)
// BM=64, BN=128, BK=16; 256 threads; 4x8 micro-tile (cols split tn*4 / 64+tn*4)
__global__ __launch_bounds__(256) void qkv_gemm_kernel(const float* __restrict__ x,
                                                       const float* __restrict__ w) {
  __shared__ float As[16][68];    // [k][m]  (68: rows 272B apart -> bank-shifted)
  __shared__ float Bs[16][132];   // [k][n]
  const int t  = threadIdx.x;
  const int m0 = blockIdx.x * 64;
  const int n0 = blockIdx.y * 128;
  const int tm = t >> 4, tn = t & 15;
  const int lk = t & 3,  lr = t >> 2;   // loader: k-chunk 0..3, row 0..63

  float acc[4][8];
#pragma unroll
  for (int r = 0; r < 4; r++)
#pragma unroll
    for (int c = 0; c < 8; c++) acc[r][c] = 0.f;

  for (int k0 = 0; k0 < HCH; k0 += 16) {
    {
      float4 v = *(const float4*)(x + (size_t)(m0 + lr) * HCH + k0 + lk * 4);
      As[lk*4+0][lr] = v.x; As[lk*4+1][lr] = v.y;
      As[lk*4+2][lr] = v.z; As[lk*4+3][lr] = v.w;
    }
#pragma unroll
    for (int p = 0; p < 2; p++) {
      int n = lr + p * 64;
      float4 v = *(const float4*)(w + (size_t)(n0 + n) * HCH + k0 + lk * 4);
      Bs[lk*4+0][n] = v.x; Bs[lk*4+1][n] = v.y;
      Bs[lk*4+2][n] = v.z; Bs[lk*4+3][n] = v.w;
    }
    __syncthreads();
#pragma unroll
    for (int kk = 0; kk < 16; kk++) {
      const float4 a  = *(const float4*)&As[kk][tm * 4];
      const float4 b0 = *(const float4*)&Bs[kk][tn * 4];
      const float4 b1 = *(const float4*)&Bs[kk][64 + tn * 4];
      acc[0][0]+=a.x*b0.x; acc[0][1]+=a.x*b0.y; acc[0][2]+=a.x*b0.z; acc[0][3]+=a.x*b0.w;
      acc[0][4]+=a.x*b1.x; acc[0][5]+=a.x*b1.y; acc[0][6]+=a.x*b1.z; acc[0][7]+=a.x*b1.w;
      acc[1][0]+=a.y*b0.x; acc[1][1]+=a.y*b0.y; acc[1][2]+=a.y*b0.z; acc[1][3]+=a.y*b0.w;
      acc[1][4]+=a.y*b1.x; acc[1][5]+=a.y*b1.y; acc[1][6]+=a.y*b1.z; acc[1][7]+=a.y*b1.w;
      acc[2][0]+=a.z*b0.x; acc[2][1]+=a.z*b0.y; acc[2][2]+=a.z*b0.z; acc[2][3]+=a.z*b0.w;
      acc[2][4]+=a.z*b1.x; acc[2][5]+=a.z*b1.y; acc[2][6]+=a.z*b1.z; acc[2][7]+=a.z*b1.w;
      acc[3][0]+=a.w*b0.x; acc[3][1]+=a.w*b0.y; acc[3][2]+=a.w*b0.z; acc[3][3]+=a.w*b0.w;
      acc[3][4]+=a.w*b1.x; acc[3][5]+=a.w*b1.y; acc[3][6]+=a.w*b1.z; acc[3][7]+=a.w*b1.w;
    }
    __syncthreads();
  }
#pragma unroll
  for (int r = 0; r < 4; r++) {
    int row = m0 + tm * 4 + r;
    float4 o0 = make_float4(acc[r][0], acc[r][1], acc[r][2], acc[r][3]);
    float4 o1 = make_float4(acc[r][4], acc[r][5], acc[r][6], acc[r][7]);
    *(float4*)(g_qkv + (size_t)row * 384 + n0 + tn * 4)      = o0;
    *(float4*)(g_qkv + (size_t)row * 384 + n0 + 64 + tn * 4) = o1;
  }
}

// ---------------- transpose q,k -> [d][token] (scale folded into Q) ----------------
__global__ __launch_bounds__(256) void transpose_qk_kernel() {
  __shared__ float tile[32][33];
  const int m0 = blockIdx.x * 32;
  const int c0 = blockIdx.y * 32;   // 0..224 (q,k cols only)
  const int x = threadIdx.x & 31, y = threadIdx.x >> 5;
  const float fscale = 1.4426950408889634f / 128.0f;  // log2(e)/D
#pragma unroll
  for (int yy = 0; yy < 32; yy += 8)
    tile[y + yy][x] = g_qkv[(size_t)(m0 + y + yy) * 384 + c0 + x];
  __syncthreads();
#pragma unroll
  for (int yy = 0; yy < 32; yy += 8) {
    int c = c0 + y + yy;
    float v = tile[x][y + yy];
    if (c < 128) g_qt[(size_t)c * NTOK + m0 + x] = v * fscale;
    else         g_kt[(size_t)(c - 128) * NTOK + m0 + x] = v;
  }
}

// ---------------- flash attention (fp32) ----------------
// grid 128 CTAs (BM=64 queries each), 256 threads; BN=64 keys per tile.
// thread (ty=t/16, tx=t%16): S fragment rows ty*4..+3, cols tx*4..+3.
__global__ __launch_bounds__(256) void attn_kernel(const unsigned char* __restrict__ mask8,
                                                   float* __restrict__ out) {
  extern __shared__ float sm[];
  float* Qs = sm;                  // [128][68]  (k-major, transposed)
  float* Ks = Qs + 128 * 68;       // [128][68]
  float* Vs = Ks + 128 * 68;       // [64][128]  (row-major)
  float* Ps = Vs + 64 * 128;       // [64][68]

  const int t = threadIdx.x;
  const int tx = t & 15, ty = t >> 4;
  const int qbase = blockIdx.x * 64;
  const bool m4 = (g_mask4 != 0);

  const int ldn = t & 15, ldd = t >> 4;   // K/Q tile loader: n-chunk, d-row
  const int vd = t & 31, vn = t >> 5;     // V tile loader

  // Q tile (once): conflict-free on both global read and smem store
#pragma unroll
  for (int p = 0; p < 8; p++) {
    int d = ldd + p * 16;
    float4 v = *(const float4*)(g_qt + (size_t)d * NTOK + qbase + ldn * 4);
    *(float4*)(Qs + d * 68 + ldn * 4) = v;
  }

  float o[4][8];
#pragma unroll
  for (int r = 0; r < 4; r++)
#pragma unroll
    for (int c = 0; c < 8; c++) o[r][c] = 0.f;
  float mrow[4] = {-1e4f, -1e4f, -1e4f, -1e4f};
  float lrow[4] = {0.f, 0.f, 0.f, 0.f};

  for (int kb = 0; kb < 128; kb++) {
    const int kbase = kb * 64;

    // ---- mask fetch first (long-latency, hidden under tile load + QK) ----
    unsigned mm[4];
    if (m4) {
      const int4* mp = (const int4*)mask8;
#pragma unroll
      for (int r = 0; r < 4; r++) {
        int idx = ((qbase + ty * 4 + r) << 13) + kbase + (tx << 2);
        int4 wv = mp[idx >> 2];
        mm[r] = (wv.x ? 1u : 0u) | (wv.y ? 0x100u : 0u) |
                (wv.z ? 0x10000u : 0u) | (wv.w ? 0x1000000u : 0u);
      }
    } else {
#pragma unroll
      for (int r = 0; r < 4; r++) {
        int idx = ((qbase + ty * 4 + r) << 13) + kbase + (tx << 2);
        mm[r] = *(const unsigned*)(mask8 + idx);
      }
    }

    // ---- K tile (transposed global -> conflict-free smem) ----
#pragma unroll
    for (int p = 0; p < 8; p++) {
      int d = ldd + p * 16;
      float4 v = *(const float4*)(g_kt + (size_t)d * NTOK + kbase + ldn * 4);
      *(float4*)(Ks + d * 68 + ldn * 4) = v;
    }
    // ---- V tile (row-major, direct) ----
#pragma unroll
    for (int p = 0; p < 8; p++) {
      int n = vn + p * 8;
      float4 v = *(const float4*)(g_qkv + (size_t)(kbase + n) * 384 + 256 + vd * 4);
      *(float4*)(Vs + n * 128 + vd * 4) = v;
    }
    __syncthreads();

    // ---- S = Q*K^T (already in log2 domain via folded scale) ----
    float s[4][4];
#pragma unroll
    for (int r = 0; r < 4; r++)
#pragma unroll
      for (int c = 0; c < 4; c++) s[r][c] = 0.f;
#pragma unroll 8
    for (int k = 0; k < 128; k++) {
      const float4 a = *(const float4*)(Qs + k * 68 + (ty << 2));
      const float4 b = *(const float4*)(Ks + k * 68 + (tx << 2));
      s[0][0]+=a.x*b.x; s[0][1]+=a.x*b.y; s[0][2]+=a.x*b.z; s[0][3]+=a.x*b.w;
      s[1][0]+=a.y*b.x; s[1][1]+=a.y*b.y; s[1][2]+=a.y*b.z; s[1][3]+=a.y*b.w;
      s[2][0]+=a.z*b.x; s[2][1]+=a.z*b.y; s[2][2]+=a.z*b.z; s[2][3]+=a.z*b.w;
      s[3][0]+=a.w*b.x; s[3][1]+=a.w*b.y; s[3][2]+=a.w*b.z; s[3][3]+=a.w*b.w;
    }

    // ---- online softmax (per-row over 16 lanes) ----
#pragma unroll
    for (int r = 0; r < 4; r++) {
#pragma unroll
      for (int c = 0; c < 4; c++)
        if ((mm[r] >> (8 * c)) & 0xffu) s[r][c] = -1e30f;
      float mx = fmaxf(fmaxf(s[r][0], s[r][1]), fmaxf(s[r][2], s[r][3]));
      mx = fmaxf(mx, __shfl_xor_sync(0xffffffffu, mx, 1));
      mx = fmaxf(mx, __shfl_xor_sync(0xffffffffu, mx, 2));
      mx = fmaxf(mx, __shfl_xor_sync(0xffffffffu, mx, 4));
      mx = fmaxf(mx, __shfl_xor_sync(0xffffffffu, mx, 8));
      float mnew = fmaxf(mrow[r], mx);
      float alpha = fexp2(mrow[r] - mnew);
      mrow[r] = mnew;
      float p0 = fexp2(s[r][0] - mnew);
      float p1 = fexp2(s[r][1] - mnew);
      float p2 = fexp2(s[r][2] - mnew);
      float p3 = fexp2(s[r][3] - mnew);
      lrow[r] = lrow[r] * alpha + (p0 + p1) + (p2 + p3);
#pragma unroll
      for (int c = 0; c < 8; c++) o[r][c] *= alpha;
      *(float4*)(Ps + (ty * 4 + r) * 68 + (tx << 2)) = make_float4(p0, p1, p2, p3);
    }
    __syncthreads();

    // ---- O += P * V (cols split tx*4 and 64+tx*4 -> conflict-free LDS.128) ----
#pragma unroll 4
    for (int j = 0; j < 64; j++) {
      const float4 v0 = *(const float4*)(Vs + j * 128 + (tx << 2));
      const float4 v1 = *(const float4*)(Vs + j * 128 + 64 + (tx << 2));
#pragma unroll
      for (int r = 0; r < 4; r++) {
        float p = Ps[(ty * 4 + r) * 68 + j];
        o[r][0] += p * v0.x; o[r][1] += p * v0.y;
        o[r][2] += p * v0.z; o[r][3] += p * v0.w;
        o[r][4] += p * v1.x; o[r][5] += p * v1.y;
        o[r][6] += p * v1.z; o[r][7] += p * v1.w;
      }
    }
    __syncthreads();
  }

  // ---- finalize: reduce l across the 16 lanes, normalize, store ----
#pragma unroll
  for (int r = 0; r < 4; r++) {
    float l = lrow[r];
    l += __shfl_xor_sync(0xffffffffu, l, 1);
    l += __shfl_xor_sync(0xffffffffu, l, 2);
    l += __shfl_xor_sync(0xffffffffu, l, 4);
    l += __shfl_xor_sync(0xffffffffu, l, 8);
    float inv = 1.0f / l;
    int row = qbase + ty * 4 + r;
    float4 o0 = make_float4(o[r][0]*inv, o[r][1]*inv, o[r][2]*inv, o[r][3]*inv);
    float4 o1 = make_float4(o[r][4]*inv, o[r][5]*inv, o[r][6]*inv, o[r][7]*inv);
    *(float4*)(out + (size_t)row * 128 + (tx << 2))      = o0;
    *(float4*)(out + (size_t)row * 128 + 64 + (tx << 2)) = o1;
  }
}

// ---------------- launch ----------------
extern "C" void kernel_launch(void* const* d_in, const int* in_sizes, int n_in,
                              void* d_out, int out_size) {
  const float* x0 = nullptr;
  const void*  mask = nullptr;
  const float* wqkv = nullptr;
  for (int i = 0; i < n_in; i++) {
    long sz = in_sizes[i];
    if (sz == (long)NTOK * HCH)            x0   = (const float*)d_in[i];
    else if (sz == (long)NTOK * NTOK)      mask = d_in[i];
    else if (sz == (long)3 * DHEAD * HCH)  wqkv = (const float*)d_in[i];
  }

  detect_mask_kernel<<<1, 32>>>((const unsigned*)mask);

  dim3 ggrid(NTOK / 64, 3);
  qkv_gemm_kernel<<<ggrid, 256>>>(x0, wqkv);

  dim3 tgrid(NTOK / 32, 8);
  transpose_qk_kernel<<<tgrid, 256>>>();

  size_t smem = (size_t)(128 * 68 + 128 * 68 + 64 * 128 + 64 * 68) * sizeof(float);
  cudaFuncSetAttribute(attn_kernel, cudaFuncAttributeMaxDynamicSharedMemorySize, (int)smem);
  attn_kernel<<<NTOK / 64, 256, smem>>>((const unsigned char*)mask, (float*)d_out);
}

// round 3
// speedup vs baseline: 5.4809x; 5.4809x over previous
#include <cuda_runtime.h>
#include <cuda_fp16.h>
#include <cstdint>

#define NTOK 8192
#define HCH  2048
#define DH   128

// ---------------- device scratch ----------------
__device__ __align__(16) __half g_xh[NTOK * HCH];
__device__ __align__(16) __half g_wh[384 * HCH];
__device__ __align__(16) __half g_qh[NTOK * DH];   // scale folded
__device__ __align__(16) __half g_kh[NTOK * DH];
__device__ __align__(16) __half g_vh[NTOK * DH];
__device__ __align__(16) float  g_O[2][NTOK * DH]; // unnormalized per split
__device__ float g_l[2][NTOK];
__device__ uint8_t g_mask8[(size_t)NTOK * NTOK];
__device__ int g_mask4;
__device__ const uint8_t* g_mptr;

// ---------------- helpers ----------------
__device__ __forceinline__ uint32_t smem_u32(const void* p) {
  uint32_t a;
  asm("{ .reg .u64 t; cvta.to.shared.u64 t, %1; cvt.u32.u64 %0, t; }" : "=r"(a) : "l"(p));
  return a;
}
__device__ __forceinline__ void ldm_x4(uint32_t* r, uint32_t a) {
  asm volatile("ldmatrix.sync.aligned.m8n8.x4.shared.b16 {%0,%1,%2,%3}, [%4];"
    : "=r"(r[0]), "=r"(r[1]), "=r"(r[2]), "=r"(r[3]) : "r"(a));
}
__device__ __forceinline__ void ldm_x2(uint32_t* r, uint32_t a) {
  asm volatile("ldmatrix.sync.aligned.m8n8.x2.shared.b16 {%0,%1}, [%2];"
    : "=r"(r[0]), "=r"(r[1]) : "r"(a));
}
__device__ __forceinline__ void ldm_x2t(uint32_t* r, uint32_t a) {
  asm volatile("ldmatrix.sync.aligned.m8n8.x2.trans.shared.b16 {%0,%1}, [%2];"
    : "=r"(r[0]), "=r"(r[1]) : "r"(a));
}
__device__ __forceinline__ void mma16816(float* d, const uint32_t* a, const uint32_t* b) {
  asm volatile("mma.sync.aligned.m16n8k16.row.col.f32.f16.f16.f32 "
    "{%0,%1,%2,%3}, {%4,%5,%6,%7}, {%8,%9}, {%0,%1,%2,%3};"
    : "+f"(d[0]), "+f"(d[1]), "+f"(d[2]), "+f"(d[3])
    : "r"(a[0]), "r"(a[1]), "r"(a[2]), "r"(a[3]), "r"(b[0]), "r"(b[1]));
}
__device__ __forceinline__ float fexp2(float x) {
  float y; asm("ex2.approx.ftz.f32 %0, %1;" : "=f"(y) : "f"(x)); return y;
}
__device__ __forceinline__ uint32_t pack_h2(float x, float y) {
  __half2 h = __floats2half2_rn(x, y);
  return *(uint32_t*)&h;
}

// ---------------- mask dtype detection ----------------
__global__ void detect_mask_kernel(const unsigned* __restrict__ m,
                                   const uint8_t* __restrict__ morig) {
  if (threadIdx.x == 0 && blockIdx.x == 0) {
    int ok = 1;
    for (int i = 0; i < 64; i++) {
      unsigned w = m[i];
      if (w > 1u && w != 0x3f800000u) { ok = 0; break; }
    }
    g_mask4 = ok;
    g_mptr = ok ? (const uint8_t*)g_mask8 : morig;
  }
}

// compact 4-byte mask -> bytes (no-op when mask already bytes)
__global__ __launch_bounds__(256) void mask_cvt_kernel(const unsigned* __restrict__ m) {
  if (!g_mask4) return;
  size_t i = (size_t)blockIdx.x * 256 + threadIdx.x;   // 16 outputs each
  const uint4* src = (const uint4*)m + i * 4;
  uint4 a = src[0], b = src[1], c = src[2], d = src[3];
  uint4 o;
  o.x = (a.x?1u:0u)|((a.y?1u:0u)<<8)|((a.z?1u:0u)<<16)|((a.w?1u:0u)<<24);
  o.y = (b.x?1u:0u)|((b.y?1u:0u)<<8)|((b.z?1u:0u)<<16)|((b.w?1u:0u)<<24);
  o.z = (c.x?1u:0u)|((c.y?1u:0u)<<8)|((c.z?1u:0u)<<16)|((c.w?1u:0u)<<24);
  o.w = (d.x?1u:0u)|((d.y?1u:0u)<<8)|((d.z?1u:0u)<<16)|((d.w?1u:0u)<<24);
  *(uint4*)(g_mask8 + i * 16) = o;
}

// ---------------- fp32 -> fp16 ----------------
__global__ __launch_bounds__(256) void cvt_kernel(const float* __restrict__ src,
                                                  __half* __restrict__ dst, int n4) {
  int i = blockIdx.x * 256 + threadIdx.x;
  if (i < n4) {
    float4 v = ((const float4*)src)[i];
    uint2 o; o.x = pack_h2(v.x, v.y); o.y = pack_h2(v.z, v.w);
    ((uint2*)dst)[i] = o;
  }
}

// ---------------- QKV GEMM (mma.sync fp16) ----------------
// grid (64, 3): 128-row tile x one of {q,k,v}. BK=64, 8 warps in 4x2.
__global__ __launch_bounds__(256) void qkv_kernel() {
  __shared__ __align__(16) char smem[32768];   // As 16KB + Bs 16KB
  const uint32_t sb = smem_u32(smem);
  const int tid = threadIdx.x, lane = tid & 31, wid = tid >> 5;
  const int wr = wid & 3, wc = wid >> 2;
  const int g = lane >> 2, c4 = lane & 3;
  const int m0 = blockIdx.x * 128;
  const int which = blockIdx.y;
  const __half* wsrc = g_wh + (size_t)which * 128 * HCH;

  float acc[2][8][4];
#pragma unroll
  for (int mt = 0; mt < 2; mt++)
#pragma unroll
    for (int nt = 0; nt < 8; nt++)
#pragma unroll
      for (int r = 0; r < 4; r++) acc[mt][nt][r] = 0.f;

  const int x7 = lane & 7, hiA = lane >> 4, hiB = (lane >> 3) & 1;
  const uint32_t aBase = sb + (uint32_t)(wr * 32 + (lane & 15)) * 128;
  const uint32_t bBase = sb + 16384 + (uint32_t)(wc * 64 + x7) * 128;

  for (int kc = 0; kc < 32; kc++) {
    __syncthreads();
#pragma unroll
    for (int i = 0; i < 4; i++) {
      int idx = tid + i * 256;
      int r = idx >> 3, ch = idx & 7;
      uint4 v = *(const uint4*)(g_xh + (size_t)(m0 + r) * HCH + kc * 64 + ch * 8);
      *(uint4*)(smem + r * 128 + ((ch ^ (r & 7)) << 4)) = v;
      uint4 w = *(const uint4*)(wsrc + (size_t)r * HCH + kc * 64 + ch * 8);
      *(uint4*)(smem + 16384 + r * 128 + ((ch ^ (r & 7)) << 4)) = w;
    }
    __syncthreads();
#pragma unroll
    for (int ks = 0; ks < 4; ks++) {
      uint32_t a0[4], a1[4];
      ldm_x4(a0, aBase + (((ks * 2 + hiA) ^ x7) << 4));
      ldm_x4(a1, aBase + 16 * 128 + (((ks * 2 + hiA) ^ x7) << 4));
#pragma unroll
      for (int nt = 0; nt < 8; nt++) {
        uint32_t b[2];
        ldm_x2(b, bBase + nt * 8 * 128 + (((ks * 2 + hiB) ^ x7) << 4));
        mma16816(acc[0][nt], a0, b);
        mma16816(acc[1][nt], a1, b);
      }
    }
  }

  const float sc = (which == 0) ? (1.4426950408889634f / 128.0f) : 1.0f;
  __half* dst = (which == 0) ? g_qh : (which == 1) ? g_kh : g_vh;
#pragma unroll
  for (int mt = 0; mt < 2; mt++)
#pragma unroll
    for (int h = 0; h < 2; h++) {
      int row = m0 + wr * 32 + mt * 16 + g + h * 8;
#pragma unroll
      for (int nt = 0; nt < 8; nt++) {
        int col = wc * 64 + nt * 8 + c4 * 2;
        *(uint32_t*)(dst + (size_t)row * DH + col) =
            pack_h2(acc[mt][nt][h * 2] * sc, acc[mt][nt][h * 2 + 1] * sc);
      }
    }
}

// ---------------- attention ----------------
// grid 128 = 64 q-tiles x 2 kv-splits. BM=BN=128, 8 warps (4 row-groups x 2 col-groups).
#define SQ 0
#define SK 32768
#define SV 65536
#define SP 98304
#define SL 131072
#define A_SMEM (131072 + 1024 + 256)

__global__ __launch_bounds__(256, 1) void attn_kernel() {
  extern __shared__ __align__(16) char smem[];
  const uint32_t sb = smem_u32(smem);
  const int tid = threadIdx.x, lane = tid & 31, wid = tid >> 5;
  const int wr = wid & 3, wc = wid >> 2;
  const int g = lane >> 2, c4 = lane & 3;
  const int qbase = (blockIdx.x >> 1) * 128;
  const int split = blockIdx.x & 1;
  const uint8_t* mp = g_mptr;

  const int x7 = lane & 7, hiA = lane >> 4, hiB = (lane >> 3) & 1;
  const uint32_t qBase = sb + SQ + (uint32_t)(wr * 32 + (lane & 15)) * 256;
  const uint32_t kBase = sb + SK + (uint32_t)(wc * 64 + x7) * 256;
  const uint32_t pBase = sb + SP + (uint32_t)(wr * 32 + (lane & 15)) * 256;
  const uint32_t vBase = sb + SV + (uint32_t)(lane & 15) * 256;

  // Q tile (once)
#pragma unroll
  for (int i = 0; i < 8; i++) {
    int idx = tid + i * 256;
    int r = idx >> 4, ch = idx & 15;
    uint4 v = *(const uint4*)(g_qh + (size_t)(qbase + r) * DH + ch * 8);
    *(uint4*)(smem + SQ + r * 256 + ((ch ^ (r & 7)) << 4)) = v;
  }

  float o[2][8][4];
#pragma unroll
  for (int mt = 0; mt < 2; mt++)
#pragma unroll
    for (int nt = 0; nt < 8; nt++)
#pragma unroll
      for (int r = 0; r < 4; r++) o[mt][nt][r] = 0.f;
  float lp[2][2] = {{0.f, 0.f}, {0.f, 0.f}};

  const uint8_t* mrow0 = mp + (size_t)(qbase + wr * 32 + g) * NTOK +
                         split * 4096 + wc * 64 + c4 * 2;

  for (int kb = 0; kb < 32; kb++) {
    const int kcol = split * 4096 + kb * 128;
    __syncthreads();
    // K, V tiles
#pragma unroll
    for (int i = 0; i < 8; i++) {
      int idx = tid + i * 256;
      int r = idx >> 4, ch = idx & 15;
      uint4 kv = *(const uint4*)(g_kh + (size_t)(kcol + r) * DH + ch * 8);
      *(uint4*)(smem + SK + r * 256 + ((ch ^ (r & 7)) << 4)) = kv;
      uint4 vv = *(const uint4*)(g_vh + (size_t)(kcol + r) * DH + ch * 8);
      *(uint4*)(smem + SV + r * 256 + ((ch ^ (r & 7)) << 4)) = vv;
    }
    __syncthreads();

    // ---- S = Q @ K^T ----
    float s[2][8][4];
#pragma unroll
    for (int mt = 0; mt < 2; mt++)
#pragma unroll
      for (int nt = 0; nt < 8; nt++)
#pragma unroll
        for (int r = 0; r < 4; r++) s[mt][nt][r] = 0.f;
#pragma unroll
    for (int ks = 0; ks < 8; ks++) {
      uint32_t a0[4], a1[4];
      ldm_x4(a0, qBase + (((ks * 2 + hiA) ^ x7) << 4));
      ldm_x4(a1, qBase + 16 * 256 + (((ks * 2 + hiA) ^ x7) << 4));
#pragma unroll
      for (int nt = 0; nt < 8; nt++) {
        uint32_t b[2];
        ldm_x2(b, kBase + nt * 8 * 256 + (((ks * 2 + hiB) ^ x7) << 4));
        mma16816(s[0][nt], a0, b);
        mma16816(s[1][nt], a1, b);
      }
    }

    // ---- masked exp2, accumulate l, write P ----
    const uint8_t* mkb = mrow0 + kb * 128;
#pragma unroll
    for (int mt = 0; mt < 2; mt++) {
      unsigned mv[2][8];
#pragma unroll
      for (int h = 0; h < 2; h++)
#pragma unroll
        for (int nt = 0; nt < 8; nt++)
          mv[h][nt] = *(const unsigned short*)(mkb + (size_t)(mt * 16 + h * 8) * NTOK + nt * 8);
#pragma unroll
      for (int h = 0; h < 2; h++) {
        int rowl = wr * 32 + mt * 16 + g + h * 8;
        uint32_t prow = sb + SP + (uint32_t)rowl * 256 + c4 * 4;
#pragma unroll
        for (int nt = 0; nt < 8; nt++) {
          float p0 = (mv[h][nt] & 0xffu) ? 0.f : fexp2(s[mt][nt][h * 2]);
          float p1 = (mv[h][nt] >> 8)    ? 0.f : fexp2(s[mt][nt][h * 2 + 1]);
          lp[mt][h] += p0 + p1;
          uint32_t off = prow + ((((wc * 8 + nt) ^ g)) << 4);
          asm volatile("st.shared.b32 [%0], %1;" :: "r"(off), "r"(pack_h2(p0, p1)));
        }
      }
    }
    __syncthreads();

    // ---- O += P @ V ----
#pragma unroll
    for (int ks = 0; ks < 8; ks++) {
      uint32_t a0[4], a1[4];
      ldm_x4(a0, pBase + (((ks * 2 + hiA) ^ x7) << 4));
      ldm_x4(a1, pBase + 16 * 256 + (((ks * 2 + hiA) ^ x7) << 4));
      uint32_t vrow = vBase + (uint32_t)(ks * 16) * 256;
#pragma unroll
      for (int nt = 0; nt < 8; nt++) {
        uint32_t b[2];
        ldm_x2t(b, vrow + (((wc * 8 + nt) ^ x7) << 4));
        mma16816(o[0][nt], a0, b);
        mma16816(o[1][nt], a1, b);
      }
    }
  }

  // ---- l reduction ----
  float* smL = (float*)(smem + SL);   // [2][128]
#pragma unroll
  for (int mt = 0; mt < 2; mt++)
#pragma unroll
    for (int h = 0; h < 2; h++) {
      float v = lp[mt][h];
      v += __shfl_xor_sync(0xffffffffu, v, 1);
      v += __shfl_xor_sync(0xffffffffu, v, 2);
      lp[mt][h] = v;
    }
  __syncthreads();
  if (c4 == 0) {
#pragma unroll
    for (int mt = 0; mt < 2; mt++)
#pragma unroll
      for (int h = 0; h < 2; h++)
        smL[wc * 128 + wr * 32 + mt * 16 + g + h * 8] = lp[mt][h];
  }
  __syncthreads();

#pragma unroll
  for (int mt = 0; mt < 2; mt++)
#pragma unroll
    for (int h = 0; h < 2; h++) {
      int rowl = wr * 32 + mt * 16 + g + h * 8;
      float lt = smL[rowl] + smL[128 + rowl];
      if (wc == 0 && c4 == 0) g_l[split][qbase + rowl] = lt;
#pragma unroll
      for (int nt = 0; nt < 8; nt++) {
        int col = wc * 64 + nt * 8 + c4 * 2;
        float2 ov = make_float2(o[mt][nt][h * 2], o[mt][nt][h * 2 + 1]);
        *(float2*)(&g_O[split][(size_t)(qbase + rowl) * DH + col]) = ov;
      }
    }
}

// ---------------- combine splits ----------------
__global__ __launch_bounds__(256) void combine_kernel(float* __restrict__ out) {
  int i = blockIdx.x * 256 + threadIdx.x;
  int row = i >> 7;
  float l = g_l[0][row] + g_l[1][row];
  out[i] = (g_O[0][i] + g_O[1][i]) / l;
}

// ---------------- launch ----------------
extern "C" void kernel_launch(void* const* d_in, const int* in_sizes, int n_in,
                              void* d_out, int out_size) {
  const float* x0 = nullptr;
  const void*  mask = nullptr;
  const float* wqkv = nullptr;
  for (int i = 0; i < n_in; i++) {
    long sz = in_sizes[i];
    if (sz == (long)NTOK * HCH)        x0   = (const float*)d_in[i];
    else if (sz == (long)NTOK * NTOK)  mask = d_in[i];
    else if (sz == (long)3 * DH * HCH) wqkv = (const float*)d_in[i];
  }

  detect_mask_kernel<<<1, 32>>>((const unsigned*)mask, (const uint8_t*)mask);
  mask_cvt_kernel<<<(int)((size_t)NTOK * NTOK / 16 / 256), 256>>>((const unsigned*)mask);

  __half* xh; cudaGetSymbolAddress((void**)&xh, g_xh);
  __half* wh; cudaGetSymbolAddress((void**)&wh, g_wh);
  cvt_kernel<<<NTOK * HCH / 4 / 256, 256>>>(x0, xh, NTOK * HCH / 4);
  cvt_kernel<<<384 * HCH / 4 / 256, 256>>>(wqkv, wh, 384 * HCH / 4);

  dim3 ggrid(NTOK / 128, 3);
  qkv_kernel<<<ggrid, 256>>>();

  cudaFuncSetAttribute(attn_kernel, cudaFuncAttributeMaxDynamicSharedMemorySize, A_SMEM);
  attn_kernel<<<NTOK / 128 * 2, 256, A_SMEM>>>();

  combine_kernel<<<NTOK * DH / 256, 256>>>((float*)d_out);
}

// round 4
// speedup vs baseline: 7.4171x; 1.3533x over previous
#include <cuda_runtime.h>
#include <cuda_fp16.h>
#include <cstdint>

#define NTOK 8192
#define HCH  2048
#define DH   128

// ---------------- device scratch ----------------
__device__ __align__(16) __half g_xh[NTOK * HCH];
__device__ __align__(16) __half g_wh[384 * HCH];
__device__ __align__(16) __half g_qh[NTOK * DH];   // scale folded
__device__ __align__(16) __half g_kh[NTOK * DH];
__device__ __align__(16) __half g_vh[NTOK * DH];
__device__ __align__(16) float  g_O[2][NTOK * DH]; // unnormalized per split
__device__ float g_l[2][NTOK];
__device__ uint8_t g_mask8[(size_t)NTOK * NTOK];
__device__ int g_mask4;
__device__ const uint8_t* g_mptr;

// ---------------- helpers ----------------
__device__ __forceinline__ uint32_t smem_u32(const void* p) {
  uint32_t a;
  asm("{ .reg .u64 t; cvta.to.shared.u64 t, %1; cvt.u32.u64 %0, t; }" : "=r"(a) : "l"(p));
  return a;
}
__device__ __forceinline__ void ldm_x4(uint32_t* r, uint32_t a) {
  asm volatile("ldmatrix.sync.aligned.m8n8.x4.shared.b16 {%0,%1,%2,%3}, [%4];"
    : "=r"(r[0]), "=r"(r[1]), "=r"(r[2]), "=r"(r[3]) : "r"(a));
}
__device__ __forceinline__ void ldm_x2(uint32_t* r, uint32_t a) {
  asm volatile("ldmatrix.sync.aligned.m8n8.x2.shared.b16 {%0,%1}, [%2];"
    : "=r"(r[0]), "=r"(r[1]) : "r"(a));
}
__device__ __forceinline__ void ldm_x2t(uint32_t* r, uint32_t a) {
  asm volatile("ldmatrix.sync.aligned.m8n8.x2.trans.shared.b16 {%0,%1}, [%2];"
    : "=r"(r[0]), "=r"(r[1]) : "r"(a));
}
__device__ __forceinline__ void stm_x4(uint32_t a, uint32_t r0, uint32_t r1,
                                       uint32_t r2, uint32_t r3) {
  asm volatile("stmatrix.sync.aligned.m8n8.x4.shared.b16 [%0], {%1,%2,%3,%4};"
    :: "r"(a), "r"(r0), "r"(r1), "r"(r2), "r"(r3) : "memory");
}
__device__ __forceinline__ void mma16816(float* d, const uint32_t* a, const uint32_t* b) {
  asm volatile("mma.sync.aligned.m16n8k16.row.col.f32.f16.f16.f32 "
    "{%0,%1,%2,%3}, {%4,%5,%6,%7}, {%8,%9}, {%0,%1,%2,%3};"
    : "+f"(d[0]), "+f"(d[1]), "+f"(d[2]), "+f"(d[3])
    : "r"(a[0]), "r"(a[1]), "r"(a[2]), "r"(a[3]), "r"(b[0]), "r"(b[1]));
}
__device__ __forceinline__ void cp16(uint32_t dst, const void* src) {
  asm volatile("cp.async.cg.shared.global [%0], [%1], 16;" :: "r"(dst), "l"(src) : "memory");
}
#define CP_COMMIT() asm volatile("cp.async.commit_group;" ::: "memory")
#define CP_WAIT0()  asm volatile("cp.async.wait_group 0;" ::: "memory")
__device__ __forceinline__ float fexp2(float x) {
  float y; asm("ex2.approx.ftz.f32 %0, %1;" : "=f"(y) : "f"(x)); return y;
}
__device__ __forceinline__ uint32_t pack_h2(float x, float y) {
  __half2 h = __floats2half2_rn(x, y);
  return *(uint32_t*)&h;
}

// ---------------- mask dtype detection ----------------
__global__ void detect_mask_kernel(const unsigned* __restrict__ m,
                                   const uint8_t* __restrict__ morig) {
  if (threadIdx.x == 0 && blockIdx.x == 0) {
    int ok = 1;
    for (int i = 0; i < 64; i++) {
      unsigned w = m[i];
      if (w > 1u && w != 0x3f800000u) { ok = 0; break; }
    }
    g_mask4 = ok;
    g_mptr = ok ? (const uint8_t*)g_mask8 : morig;
  }
}

// compact 4-byte mask -> bytes (no-op when mask already bytes)
__global__ __launch_bounds__(256) void mask_cvt_kernel(const unsigned* __restrict__ m) {
  if (!g_mask4) return;
  size_t i = (size_t)blockIdx.x * 256 + threadIdx.x;   // 16 outputs each
  const uint4* src = (const uint4*)m + i * 4;
  uint4 a = src[0], b = src[1], c = src[2], d = src[3];
  uint4 o;
  o.x = (a.x?1u:0u)|((a.y?1u:0u)<<8)|((a.z?1u:0u)<<16)|((a.w?1u:0u)<<24);
  o.y = (b.x?1u:0u)|((b.y?1u:0u)<<8)|((b.z?1u:0u)<<16)|((b.w?1u:0u)<<24);
  o.z = (c.x?1u:0u)|((c.y?1u:0u)<<8)|((c.z?1u:0u)<<16)|((c.w?1u:0u)<<24);
  o.w = (d.x?1u:0u)|((d.y?1u:0u)<<8)|((d.z?1u:0u)<<16)|((d.w?1u:0u)<<24);
  *(uint4*)(g_mask8 + i * 16) = o;
}

// ---------------- fp32 -> fp16 ----------------
__global__ __launch_bounds__(256) void cvt_kernel(const float* __restrict__ src,
                                                  __half* __restrict__ dst, int n4) {
  int i = blockIdx.x * 256 + threadIdx.x;
  if (i < n4) {
    float4 v = ((const float4*)src)[i];
    uint2 o; o.x = pack_h2(v.x, v.y); o.y = pack_h2(v.z, v.w);
    ((uint2*)dst)[i] = o;
  }
}

// ---------------- QKV GEMM (mma.sync fp16, cp.async double-buffered) ----------------
// grid (64, 3). BK=64; smem 2 x (A 16KB + B 16KB) = 64KB.
__global__ __launch_bounds__(256) void qkv_kernel() {
  extern __shared__ __align__(16) char smem[];
  const uint32_t sb = smem_u32(smem);
  const int tid = threadIdx.x, lane = tid & 31, wid = tid >> 5;
  const int wr = wid & 3, wc = wid >> 2;
  const int g = lane >> 2, c4 = lane & 3;
  const int m0 = blockIdx.x * 128;
  const int which = blockIdx.y;
  const __half* wsrc = g_wh + (size_t)which * 128 * HCH;

  float acc[2][8][4];
#pragma unroll
  for (int mt = 0; mt < 2; mt++)
#pragma unroll
    for (int nt = 0; nt < 8; nt++)
#pragma unroll
      for (int r = 0; r < 4; r++) acc[mt][nt][r] = 0.f;

  const int x7 = lane & 7, hiA = lane >> 4, hiB = (lane >> 3) & 1;

  auto issue = [&](int kc) {
    uint32_t base = sb + (uint32_t)(kc & 1) * 16384;
#pragma unroll
    for (int i = 0; i < 4; i++) {
      int idx = tid + i * 256;
      int r = idx >> 3, ch = idx & 7;
      uint32_t sw = (uint32_t)r * 128 + (uint32_t)((ch ^ (r & 7)) << 4);
      cp16(base + sw, g_xh + (size_t)(m0 + r) * HCH + kc * 64 + ch * 8);
      cp16(base + 32768 + sw, wsrc + (size_t)r * HCH + kc * 64 + ch * 8);
    }
    CP_COMMIT();
  };

  issue(0);
  for (int kc = 0; kc < 32; kc++) {
    CP_WAIT0();
    __syncthreads();
    if (kc < 31) issue(kc + 1);
    const uint32_t buf = sb + (uint32_t)(kc & 1) * 16384;
    const uint32_t aBase = buf + (uint32_t)(wr * 32 + (lane & 15)) * 128;
    const uint32_t bBase = buf + 32768 + (uint32_t)(wc * 64 + x7) * 128;
#pragma unroll
    for (int ks = 0; ks < 4; ks++) {
      uint32_t a0[4], a1[4];
      ldm_x4(a0, aBase + (((ks * 2 + hiA) ^ x7) << 4));
      ldm_x4(a1, aBase + 16 * 128 + (((ks * 2 + hiA) ^ x7) << 4));
#pragma unroll
      for (int nt = 0; nt < 8; nt++) {
        uint32_t b[2];
        ldm_x2(b, bBase + nt * 8 * 128 + (((ks * 2 + hiB) ^ x7) << 4));
        mma16816(acc[0][nt], a0, b);
        mma16816(acc[1][nt], a1, b);
      }
    }
  }

  const float sc = (which == 0) ? (1.4426950408889634f / 128.0f) : 1.0f;
  __half* dst = (which == 0) ? g_qh : (which == 1) ? g_kh : g_vh;
#pragma unroll
  for (int mt = 0; mt < 2; mt++)
#pragma unroll
    for (int h = 0; h < 2; h++) {
      int row = m0 + wr * 32 + mt * 16 + g + h * 8;
#pragma unroll
      for (int nt = 0; nt < 8; nt++) {
        int col = wc * 64 + nt * 8 + c4 * 2;
        *(uint32_t*)(dst + (size_t)row * DH + col) =
            pack_h2(acc[mt][nt][h * 2] * sc, acc[mt][nt][h * 2 + 1] * sc);
      }
    }
}

// ---------------- attention ----------------
// grid 128 = 64 q-tiles x 2 kv-splits. BM=BN=128, 8 warps (4x2).
// smem: K 2x32KB, V 2x32KB, P 32KB (Q staging in prologue), mask 2x16KB, L 1KB.
#define SK 0
#define SV 65536
#define SP 131072
#define SM 163840
#define SL 196608
#define A_SMEM (196608 + 1024)

__global__ __launch_bounds__(256, 1) void attn_kernel() {
  extern __shared__ __align__(16) char smem[];
  const uint32_t sb = smem_u32(smem);
  const int tid = threadIdx.x, lane = tid & 31, wid = tid >> 5;
  const int wr = wid & 3, wc = wid >> 2;
  const int g = lane >> 2, c4 = lane & 3;
  const int qbase = (blockIdx.x >> 1) * 128;
  const int split = blockIdx.x & 1;
  const uint8_t* mp = g_mptr;

  const int x7 = lane & 7, hiA = lane >> 4, hiB = (lane >> 3) & 1;

  auto issue = [&](int kb) {
    const int kcol = split * 4096 + kb * 128;
    const uint32_t kB = sb + SK + (uint32_t)(kb & 1) * 32768;
    const uint32_t vB = sb + SV + (uint32_t)(kb & 1) * 32768;
    const uint32_t mB = sb + SM + (uint32_t)(kb & 1) * 16384;
#pragma unroll
    for (int i = 0; i < 8; i++) {
      int idx = tid + i * 256;
      int r = idx >> 4, ch = idx & 15;
      uint32_t sw = (uint32_t)r * 256 + (uint32_t)((ch ^ (r & 7)) << 4);
      cp16(kB + sw, g_kh + (size_t)(kcol + r) * DH + ch * 8);
      cp16(vB + sw, g_vh + (size_t)(kcol + r) * DH + ch * 8);
    }
#pragma unroll
    for (int i = 0; i < 4; i++) {
      int idx = tid + i * 256;
      int r = idx >> 3, ch = idx & 7;
      cp16(mB + (uint32_t)r * 128 + (uint32_t)((ch ^ (r & 7)) << 4),
           mp + (size_t)(qbase + r) * NTOK + kcol + ch * 16);
    }
    CP_COMMIT();
  };

  // kick off kb=0 loads immediately
  issue(0);

  // stage Q into the P region, extract fragments into registers
#pragma unroll
  for (int i = 0; i < 8; i++) {
    int idx = tid + i * 256;
    int r = idx >> 4, ch = idx & 15;
    uint4 v = *(const uint4*)(g_qh + (size_t)(qbase + r) * DH + ch * 8);
    *(uint4*)(smem + SP + r * 256 + ((ch ^ (r & 7)) << 4)) = v;
  }
  __syncthreads();
  uint32_t qa[8][2][4];
  {
    const uint32_t qB = sb + SP + (uint32_t)(wr * 32 + (lane & 15)) * 256;
#pragma unroll
    for (int ks = 0; ks < 8; ks++) {
      ldm_x4(qa[ks][0], qB + (((ks * 2 + hiA) ^ x7) << 4));
      ldm_x4(qa[ks][1], qB + 16 * 256 + (((ks * 2 + hiA) ^ x7) << 4));
    }
  }

  float o[2][8][4];
#pragma unroll
  for (int mt = 0; mt < 2; mt++)
#pragma unroll
    for (int nt = 0; nt < 8; nt++)
#pragma unroll
      for (int r = 0; r < 4; r++) o[mt][nt][r] = 0.f;
  float lp[2][2] = {{0.f, 0.f}, {0.f, 0.f}};

  const int t8 = lane >> 3;            // stmatrix tile index
  const int hh = t8 & 1, ntp = t8 >> 1, r8 = lane & 7;

  for (int kb = 0; kb < 32; kb++) {
    CP_WAIT0();
    __syncthreads();                    // buffers[kb&1] ready; P readable/writable
    if (kb < 31) issue(kb + 1);

    const uint32_t kB = sb + SK + (uint32_t)(kb & 1) * 32768 + (uint32_t)(wc * 64 + x7) * 256;
    const uint32_t vB = sb + SV + (uint32_t)(kb & 1) * 32768 + (uint32_t)(lane & 15) * 256;
    const uint32_t mB = sb + SM + (uint32_t)(kb & 1) * 16384;

    // ---- S = Q @ K^T ----
    float s[2][8][4];
#pragma unroll
    for (int mt = 0; mt < 2; mt++)
#pragma unroll
      for (int nt = 0; nt < 8; nt++)
#pragma unroll
        for (int r = 0; r < 4; r++) s[mt][nt][r] = 0.f;
#pragma unroll
    for (int ks = 0; ks < 8; ks++) {
#pragma unroll
      for (int nt = 0; nt < 8; nt++) {
        uint32_t b[2];
        ldm_x2(b, kB + nt * 8 * 256 + (((ks * 2 + hiB) ^ x7) << 4));
        mma16816(s[0][nt], qa[ks][0], b);
        mma16816(s[1][nt], qa[ks][1], b);
      }
    }

    // ---- masked exp2, accumulate l, stmatrix P ----
#pragma unroll
    for (int mt = 0; mt < 2; mt++) {
      uint32_t pk[2][8];
#pragma unroll
      for (int h = 0; h < 2; h++) {
        int rowl = wr * 32 + mt * 16 + h * 8 + g;
        uint32_t rbase = mB + (uint32_t)rowl * 128;
        int r7 = rowl & 7;
#pragma unroll
        for (int nt = 0; nt < 8; nt++) {
          int bcol = wc * 64 + nt * 8 + c4 * 2;
          uint32_t maddr = rbase + (uint32_t)(((bcol >> 4) ^ r7) << 4) + (bcol & 15);
          unsigned short mv;
          asm volatile("ld.shared.u16 %0, [%1];" : "=h"(mv) : "r"(maddr));
          float p0 = (mv & 0xffu) ? 0.f : fexp2(s[mt][nt][h * 2]);
          float p1 = (mv >> 8)    ? 0.f : fexp2(s[mt][nt][h * 2 + 1]);
          lp[mt][h] += p0 + p1;
          pk[h][nt] = pack_h2(p0, p1);
        }
      }
      // 4 stmatrix.x4: tiles (h0,2j),(h1,2j),(h0,2j+1),(h1,2j+1)
      int srow = wr * 32 + mt * 16 + hh * 8 + r8;
      uint32_t sbase = sb + SP + (uint32_t)srow * 256;
      int sr7 = srow & 7;
#pragma unroll
      for (int j = 0; j < 4; j++) {
        int ntj = 2 * j + ntp;
        uint32_t addr = sbase + (uint32_t)(((wc * 8 + ntj) ^ sr7) << 4);
        stm_x4(addr, pk[0][2 * j], pk[1][2 * j], pk[0][2 * j + 1], pk[1][2 * j + 1]);
      }
    }
    __syncthreads();

    // ---- O += P @ V ----
    const uint32_t pB = sb + SP + (uint32_t)(wr * 32 + (lane & 15)) * 256;
#pragma unroll
    for (int ks = 0; ks < 8; ks++) {
      uint32_t a0[4], a1[4];
      ldm_x4(a0, pB + (((ks * 2 + hiA) ^ x7) << 4));
      ldm_x4(a1, pB + 16 * 256 + (((ks * 2 + hiA) ^ x7) << 4));
      uint32_t vrow = vB + (uint32_t)(ks * 16) * 256;
#pragma unroll
      for (int nt = 0; nt < 8; nt++) {
        uint32_t b[2];
        ldm_x2t(b, vrow + (((wc * 8 + nt) ^ x7) << 4));
        mma16816(o[0][nt], a0, b);
        mma16816(o[1][nt], a1, b);
      }
    }
  }

  // ---- l reduction ----
  float* smL = (float*)(smem + SL);   // [2][128]
#pragma unroll
  for (int mt = 0; mt < 2; mt++)
#pragma unroll
    for (int h = 0; h < 2; h++) {
      float v = lp[mt][h];
      v += __shfl_xor_sync(0xffffffffu, v, 1);
      v += __shfl_xor_sync(0xffffffffu, v, 2);
      lp[mt][h] = v;
    }
  __syncthreads();
  if (c4 == 0) {
#pragma unroll
    for (int mt = 0; mt < 2; mt++)
#pragma unroll
      for (int h = 0; h < 2; h++)
        smL[wc * 128 + wr * 32 + mt * 16 + g + h * 8] = lp[mt][h];
  }
  __syncthreads();

#pragma unroll
  for (int mt = 0; mt < 2; mt++)
#pragma unroll
    for (int h = 0; h < 2; h++) {
      int rowl = wr * 32 + mt * 16 + g + h * 8;
      float lt = smL[rowl] + smL[128 + rowl];
      if (wc == 0 && c4 == 0) g_l[split][qbase + rowl] = lt;
#pragma unroll
      for (int nt = 0; nt < 8; nt++) {
        int col = wc * 64 + nt * 8 + c4 * 2;
        float2 ov = make_float2(o[mt][nt][h * 2], o[mt][nt][h * 2 + 1]);
        *(float2*)(&g_O[split][(size_t)(qbase + rowl) * DH + col]) = ov;
      }
    }
}

// ---------------- combine splits ----------------
__global__ __launch_bounds__(256) void combine_kernel(float* __restrict__ out) {
  int i = blockIdx.x * 256 + threadIdx.x;
  int row = i >> 7;
  float l = g_l[0][row] + g_l[1][row];
  out[i] = (g_O[0][i] + g_O[1][i]) / l;
}

// ---------------- launch ----------------
extern "C" void kernel_launch(void* const* d_in, const int* in_sizes, int n_in,
                              void* d_out, int out_size) {
  const float* x0 = nullptr;
  const void*  mask = nullptr;
  const float* wqkv = nullptr;
  for (int i = 0; i < n_in; i++) {
    long sz = in_sizes[i];
    if (sz == (long)NTOK * HCH)        x0   = (const float*)d_in[i];
    else if (sz == (long)NTOK * NTOK)  mask = d_in[i];
    else if (sz == (long)3 * DH * HCH) wqkv = (const float*)d_in[i];
  }

  detect_mask_kernel<<<1, 32>>>((const unsigned*)mask, (const uint8_t*)mask);
  mask_cvt_kernel<<<(int)((size_t)NTOK * NTOK / 16 / 256), 256>>>((const unsigned*)mask);

  __half* xh; cudaGetSymbolAddress((void**)&xh, g_xh);
  __half* wh; cudaGetSymbolAddress((void**)&wh, g_wh);
  cvt_kernel<<<NTOK * HCH / 4 / 256, 256>>>(x0, xh, NTOK * HCH / 4);
  cvt_kernel<<<384 * HCH / 4 / 256, 256>>>(wqkv, wh, 384 * HCH / 4);

  cudaFuncSetAttribute(qkv_kernel, cudaFuncAttributeMaxDynamicSharedMemorySize, 65536);
  dim3 ggrid(NTOK / 128, 3);
  qkv_kernel<<<ggrid, 256, 65536>>>();

  cudaFuncSetAttribute(attn_kernel, cudaFuncAttributeMaxDynamicSharedMemorySize, A_SMEM);
  attn_kernel<<<NTOK / 128 * 2, 256, A_SMEM>>>();

  combine_kernel<<<NTOK * DH / 256, 256>>>((float*)d_out);
}